// round 4
// baseline (speedup 1.0000x reference)
#include <cuda_runtime.h>
#include <math.h>

#define Nn    10000
#define FIN   512
#define Hh    8
#define C1v   30
#define F1v   (Hh*C1v)   /* 240 */
#define CHv   64
#define F2v   (Hh*CHv)   /* 512 */
#define NCLSv 64
#define EMAX  160000
#define ETOT  (EMAX+Nn)  /* 170000 */

// ---------------- scratch (device globals; no cudaMalloc allowed) ----------
__device__ float g_h1pre[Nn*F1v];
__device__ float g_acc1 [Nn*F1v];
__device__ float g_h2pre[Nn*F2v];
__device__ float g_asrc [Nn*Hh];
__device__ float g_adst [Nn*Hh];
__device__ float g_m    [Nn*Hh];
__device__ float g_s    [Nn*Hh];
__device__ float g_alpha[ETOT*Hh];
__device__ int   g_is64;

// ---------------- helpers --------------------------------------------------
__device__ __forceinline__ void atomicMaxF(float* addr, float val) {
    int old = __float_as_int(*addr);
    while (__int_as_float(old) < val) {
        int assumed = old;
        old = atomicCAS((int*)addr, assumed, __float_as_int(val));
        if (old == assumed) break;
    }
}

__device__ __forceinline__ void get_edge(const void* ei, int E, int e, int& s, int& d) {
    if (e >= E) { s = d = e - E; return; }
    if (g_is64) {
        const long long* p = (const long long*)ei;
        s = (int)p[e]; d = (int)p[E + e];
    } else {
        const int* p = (const int*)ei;
        s = p[e]; d = p[E + e];
    }
}

// detect whether edge_index is int64 or int32 (jax x64 ambiguity).
// If data is int32, an int64 read packs two random indices -> >= 2^32 almost surely.
__global__ void k_detect_idx(const void* ei) {
    if (threadIdx.x == 0 && blockIdx.x == 0) {
        const long long* p = (const long long*)ei;
        int ok = 1;
        for (int i = 0; i < 16; i++) {
            long long v = p[i];
            if (v < 0 || v >= Nn) ok = 0;
        }
        g_is64 = ok;
    }
}

// ---------------- GEMM: C[M,Nc] = A[M,K] @ B[K,Nc] (+bias) -----------------
#define TILE 32
__global__ void k_sgemm(const float* __restrict__ A, const float* __restrict__ B,
                        float* __restrict__ C, int M, int K, int Nc,
                        const float* __restrict__ bias) {
    __shared__ float As[TILE][TILE+1];
    __shared__ float Bs[TILE][TILE+1];
    int tx = threadIdx.x, ty = threadIdx.y;
    int row = blockIdx.y * TILE + ty;
    int col = blockIdx.x * TILE + tx;
    float acc = 0.f;
    for (int k0 = 0; k0 < K; k0 += TILE) {
        As[ty][tx] = (row < M && (k0 + tx) < K) ? A[(long)row*K + k0 + tx] : 0.f;
        Bs[ty][tx] = ((k0 + ty) < K && col < Nc) ? B[(long)(k0 + ty)*Nc + col] : 0.f;
        __syncthreads();
        #pragma unroll
        for (int kk = 0; kk < TILE; kk++) acc += As[ty][kk] * Bs[kk][tx];
        __syncthreads();
    }
    if (row < M && col < Nc)
        C[(long)row*Nc + col] = acc + (bias ? bias[col] : 0.f);
}

// per-(node,head) attention coefficients
__global__ void k_attn_coef(const float* __restrict__ hpre,
                            const float* __restrict__ a_src,
                            const float* __restrict__ a_dst,
                            float* __restrict__ asrc, float* __restrict__ adst,
                            int C, int F) {
    int i = blockIdx.x * blockDim.x + threadIdx.x;
    if (i >= Nn * Hh) return;
    int n = i / Hh, hh = i % Hh;
    const float* hp = hpre + (long)n*F + hh*C;
    const float* as = a_src + hh*C;
    const float* ad = a_dst + hh*C;
    float s1 = 0.f, s2 = 0.f;
    for (int c = 0; c < C; c++) { float v = hp[c]; s1 += v*as[c]; s2 += v*ad[c]; }
    asrc[i] = s1; adst[i] = s2;
}

__global__ void k_init_ms() {
    int i = blockIdx.x * blockDim.x + threadIdx.x;
    if (i >= Nn * Hh) return;
    g_m[i] = -INFINITY;
    g_s[i] = 0.f;
}

__global__ void k_edge_alpha(const void* ei, int E) {
    int i = blockIdx.x * blockDim.x + threadIdx.x;
    int tot = (E + Nn) * Hh;
    if (i >= tot) return;
    int e = i / Hh, hh = i % Hh;
    int s, d; get_edge(ei, E, e, s, d);
    float a = g_asrc[s*Hh + hh] + g_adst[d*Hh + hh];
    a = (a > 0.f) ? a : 0.2f * a;      // leaky_relu 0.2
    g_alpha[i] = a;
    atomicMaxF(&g_m[d*Hh + hh], a);
}

__global__ void k_edge_exp(const void* ei, int E) {
    int i = blockIdx.x * blockDim.x + threadIdx.x;
    int tot = (E + Nn) * Hh;
    if (i >= tot) return;
    int e = i / Hh, hh = i % Hh;
    int s, d; get_edge(ei, E, e, s, d);
    float v = expf(g_alpha[i] - g_m[d*Hh + hh]);
    g_alpha[i] = v;
    atomicAdd(&g_s[d*Hh + hh], v);
}

__global__ void k_edge_div(const void* ei, int E) {
    int i = blockIdx.x * blockDim.x + threadIdx.x;
    int tot = (E + Nn) * Hh;
    if (i >= tot) return;
    int e = i / Hh, hh = i % Hh;
    int s, d; get_edge(ei, E, e, s, d);
    g_alpha[i] = g_alpha[i] / (g_s[d*Hh + hh] + 1e-16f);
}

// block per edge; threads sweep features; atomic scatter into acc[dst]
__global__ void k_edge_agg(const void* ei, int E,
                           const float* __restrict__ hpre,
                           float* __restrict__ acc, int C, int F) {
    int e = blockIdx.x;
    __shared__ int ss, sd;
    __shared__ float w[Hh];
    if (threadIdx.x == 0) { int a, b; get_edge(ei, E, e, a, b); ss = a; sd = b; }
    if (threadIdx.x < Hh) w[threadIdx.x] = g_alpha[e*Hh + threadIdx.x];
    __syncthreads();
    const float* hs = hpre + (long)ss*F;
    float* ad = acc + (long)sd*F;
    for (int f = threadIdx.x; f < F; f += blockDim.x)
        atomicAdd(&ad[f], w[f / C] * hs[f]);
}

__global__ void k_zero(float* p, long n) {
    long i = (long)blockIdx.x * blockDim.x + threadIdx.x;
    if (i < n) p[i] = 0.f;
}

__global__ void k_bias_elu(float* p, const float* __restrict__ b, int F, long n) {
    long i = (long)blockIdx.x * blockDim.x + threadIdx.x;
    if (i >= n) return;
    float v = p[i] + b[i % F];
    p[i] = (v > 0.f) ? v : expm1f(v);   // ELU, alpha=1
}

__global__ void k_bias_add(float* p, const float* __restrict__ b, int F, long n) {
    long i = (long)blockIdx.x * blockDim.x + threadIdx.x;
    if (i >= n) return;
    p[i] = p[i] + b[i % F];
}

static inline int cdiv(long a, int b) { return (int)((a + b - 1) / b); }

extern "C" void kernel_launch(void* const* d_in, const int* in_sizes, int n_in,
                              void* d_out, int out_size) {
    const float* x    = (const float*)d_in[0];
    const void*  ei   = d_in[1];
    const float* W1   = (const float*)d_in[2];
    const float* a1s  = (const float*)d_in[3];
    const float* a1d  = (const float*)d_in[4];
    const float* b1   = (const float*)d_in[5];
    const float* W2   = (const float*)d_in[6];
    const float* a2s  = (const float*)d_in[7];
    const float* a2d  = (const float*)d_in[8];
    const float* b2   = (const float*)d_in[9];
    const float* Wlin = (const float*)d_in[10];
    const float* blin = (const float*)d_in[11];

    int E = in_sizes[1] / 2;
    float* out  = (float*)d_out;              // [N, NCLS]
    float* hout = out + (long)Nn * NCLSv;     // [N, F2]

    float *p_h1pre, *p_acc1, *p_h2pre, *p_asrc, *p_adst;
    cudaGetSymbolAddress((void**)&p_h1pre, g_h1pre);
    cudaGetSymbolAddress((void**)&p_acc1,  g_acc1);
    cudaGetSymbolAddress((void**)&p_h2pre, g_h2pre);
    cudaGetSymbolAddress((void**)&p_asrc,  g_asrc);
    cudaGetSymbolAddress((void**)&p_adst,  g_adst);

    dim3 tb(TILE, TILE);
    int tot = (E + Nn) * Hh;

    k_detect_idx<<<1, 32>>>(ei);

    // ---- layer 1 ----
    k_sgemm<<<dim3(cdiv(F1v, TILE), cdiv(Nn, TILE)), tb>>>(x, W1, p_h1pre, Nn, FIN, F1v, nullptr);
    k_attn_coef<<<cdiv(Nn*Hh, 256), 256>>>(p_h1pre, a1s, a1d, p_asrc, p_adst, C1v, F1v);
    k_init_ms<<<cdiv(Nn*Hh, 256), 256>>>();
    k_edge_alpha<<<cdiv(tot, 256), 256>>>(ei, E);
    k_edge_exp  <<<cdiv(tot, 256), 256>>>(ei, E);
    k_edge_div  <<<cdiv(tot, 256), 256>>>(ei, E);
    k_zero<<<cdiv((long)Nn*F1v, 256), 256>>>(p_acc1, (long)Nn*F1v);
    k_edge_agg<<<E + Nn, 256>>>(ei, E, p_h1pre, p_acc1, C1v, F1v);
    k_bias_elu<<<cdiv((long)Nn*F1v, 256), 256>>>(p_acc1, b1, F1v, (long)Nn*F1v);

    // ---- layer 2 ----
    k_sgemm<<<dim3(cdiv(F2v, TILE), cdiv(Nn, TILE)), tb>>>(p_acc1, W2, p_h2pre, Nn, F1v, F2v, nullptr);
    k_attn_coef<<<cdiv(Nn*Hh, 256), 256>>>(p_h2pre, a2s, a2d, p_asrc, p_adst, CHv, F2v);
    k_init_ms<<<cdiv(Nn*Hh, 256), 256>>>();
    k_edge_alpha<<<cdiv(tot, 256), 256>>>(ei, E);
    k_edge_exp  <<<cdiv(tot, 256), 256>>>(ei, E);
    k_edge_div  <<<cdiv(tot, 256), 256>>>(ei, E);
    k_zero<<<cdiv((long)Nn*F2v, 256), 256>>>(hout, (long)Nn*F2v);
    k_edge_agg<<<E + Nn, 256>>>(ei, E, p_h2pre, hout, CHv, F2v);
    k_bias_add<<<cdiv((long)Nn*F2v, 256), 256>>>(hout, b2, F2v, (long)Nn*F2v);

    // ---- classifier head ----
    k_sgemm<<<dim3(cdiv(NCLSv, TILE), cdiv(Nn, TILE)), tb>>>(hout, Wlin, out, Nn, F2v, NCLSv, blin);
}

// round 6
// speedup vs baseline: 3.0992x; 3.0992x over previous
#include <cuda_runtime.h>
#include <math.h>

#define Nn    10000
#define FIN   512
#define Hh    8
#define C1v   30
#define F1v   (Hh*C1v)   /* 240 */
#define CHv   64
#define F2v   (Hh*CHv)   /* 512 */
#define NCLSv 64
#define EMAX  160000
#define ETOT  (EMAX+Nn)  /* 170000 */

// ---------------- scratch (device globals; no cudaMalloc allowed) ----------
__device__ float g_h1pre[Nn*F1v];
__device__ float g_acc1 [Nn*F1v];
__device__ float g_h2pre[Nn*F2v];
__device__ float g_asrc [Nn*Hh];
__device__ float g_adst [Nn*Hh];
__device__ int   g_cnt     [Nn];
__device__ int   g_cursor  [Nn];
__device__ int   g_rowstart[Nn+1];
__device__ int   g_esrc[ETOT];
__device__ int   g_edst[ETOT];
__device__ int   g_csrc[ETOT];
__device__ int   g_is64;

// ---------------- helpers --------------------------------------------------
__device__ __forceinline__ void get_edge(const void* ei, int E, int e, int& s, int& d) {
    if (e >= E) { s = d = e - E; return; }
    if (g_is64) {
        const long long* p = (const long long*)ei;
        s = (int)p[e]; d = (int)p[E + e];
    } else {
        const int* p = (const int*)ei;
        s = p[e]; d = p[E + e];
    }
}

__device__ __forceinline__ void atomicMaxFs(float* a, float v) {
    int* ai = (int*)a;
    int old = *ai;
    while (__int_as_float(old) < v) {
        int assumed = old;
        old = atomicCAS(ai, assumed, __float_as_int(v));
        if (old == assumed) break;
    }
}

// detect whether edge_index is int64 or int32 (jax x64 ambiguity)
__global__ void k_detect_idx(const void* ei) {
    if (threadIdx.x == 0 && blockIdx.x == 0) {
        const long long* p = (const long long*)ei;
        int ok = 1;
        for (int i = 0; i < 16; i++) {
            long long v = p[i];
            if (v < 0 || v >= Nn) ok = 0;
        }
        g_is64 = ok;
    }
}

// ---------------- CSR build ------------------------------------------------
__global__ void k_prep(const void* ei, int E) {
    int e = blockIdx.x * blockDim.x + threadIdx.x;
    if (e >= E + Nn) return;
    int s, d; get_edge(ei, E, e, s, d);
    g_esrc[e] = s; g_edst[e] = d;
    atomicAdd(&g_cnt[d], 1);
}

__global__ void k_scan() {
    __shared__ int sm[1024];
    __shared__ int carry;
    int t = threadIdx.x;
    if (t == 0) carry = 0;
    __syncthreads();
    for (int base = 0; base < Nn; base += 1024) {
        int v = (base + t < Nn) ? g_cnt[base + t] : 0;
        int orig = v;
        sm[t] = v;
        __syncthreads();
        for (int off = 1; off < 1024; off <<= 1) {
            int add = (t >= off) ? sm[t - off] : 0;
            __syncthreads();
            sm[t] += add;
            __syncthreads();
        }
        if (base + t < Nn) {
            int rs = carry + sm[t] - orig;   // exclusive
            g_rowstart[base + t] = rs;
            g_cursor[base + t] = rs;
        }
        __syncthreads();
        if (t == 0) carry += sm[1023];
        __syncthreads();
    }
    if (t == 0) g_rowstart[Nn] = carry;
}

__global__ void k_scatter(int tot) {
    int e = blockIdx.x * blockDim.x + threadIdx.x;
    if (e >= tot) return;
    int d = g_edst[e];
    int pos = atomicAdd(&g_cursor[d], 1);
    g_csrc[pos] = g_esrc[e];
}

// ---------------- GEMM: C[M,Nc] = A[M,K] @ B[K,Nc] (+bias) -----------------
// 64x64 block tile, 16-deep K tile, 256 threads, 4x4 micro-tile.
// Requires K % 16 == 0 and Nc % 4 == 0 (true for all three GEMMs here).
#define BM 64
#define BN 64
#define BK 16
__global__ __launch_bounds__(256) void k_sgemm(
        const float* __restrict__ A, const float* __restrict__ B,
        float* __restrict__ C, int M, int K, int Nc,
        const float* __restrict__ bias) {
    __shared__ float As[BK][BM];
    __shared__ float Bs[BK][BN];
    int tid = threadIdx.x;
    int tx = tid & 15, ty = tid >> 4;
    int row0 = blockIdx.y * BM, col0 = blockIdx.x * BN;

    float acc[4][4] = {};
    // A tile load mapping: 64 rows x 16 k; thread -> row = tid/4, 4 k-floats at (tid%4)*4
    int ar = tid >> 2, ac = (tid & 3) * 4;
    // B tile load mapping: 16 k x 64 cols; thread -> k = tid/16, 4 cols at (tid%16)*4
    int bk = tid >> 4, bc = (tid & 15) * 4;

    for (int k0 = 0; k0 < K; k0 += BK) {
        float4 av = make_float4(0.f, 0.f, 0.f, 0.f);
        if (row0 + ar < M)
            av = *(const float4*)&A[(long)(row0 + ar) * K + k0 + ac];
        As[ac + 0][ar] = av.x; As[ac + 1][ar] = av.y;
        As[ac + 2][ar] = av.z; As[ac + 3][ar] = av.w;

        float4 bv = make_float4(0.f, 0.f, 0.f, 0.f);
        if (col0 + bc < Nc)
            bv = *(const float4*)&B[(long)(k0 + bk) * Nc + col0 + bc];
        *(float4*)&Bs[bk][bc] = bv;
        __syncthreads();

        #pragma unroll
        for (int kk = 0; kk < BK; kk++) {
            float a[4], b[4];
            #pragma unroll
            for (int i = 0; i < 4; i++) a[i] = As[kk][ty * 4 + i];
            #pragma unroll
            for (int j = 0; j < 4; j++) b[j] = Bs[kk][tx * 4 + j];
            #pragma unroll
            for (int i = 0; i < 4; i++)
                #pragma unroll
                for (int j = 0; j < 4; j++)
                    acc[i][j] += a[i] * b[j];
        }
        __syncthreads();
    }

    #pragma unroll
    for (int i = 0; i < 4; i++) {
        int r = row0 + ty * 4 + i;
        if (r >= M) continue;
        #pragma unroll
        for (int j = 0; j < 4; j++) {
            int c = col0 + tx * 4 + j;
            if (c < Nc)
                C[(long)r * Nc + c] = acc[i][j] + (bias ? bias[c] : 0.f);
        }
    }
}

// per-(node,head) attention coefficients
__global__ void k_attn_coef(const float* __restrict__ hpre,
                            const float* __restrict__ a_src,
                            const float* __restrict__ a_dst,
                            int C, int F) {
    int i = blockIdx.x * blockDim.x + threadIdx.x;
    if (i >= Nn * Hh) return;
    int n = i / Hh, hh = i % Hh;
    const float* hp = hpre + (long)n * F + hh * C;
    const float* as = a_src + hh * C;
    const float* ad = a_dst + hh * C;
    float s1 = 0.f, s2 = 0.f;
    for (int c = 0; c < C; c++) { float v = hp[c]; s1 += v * as[c]; s2 += v * ad[c]; }
    g_asrc[i] = s1; g_adst[i] = s2;
}

// ---------------- fused per-node softmax + aggregate ------------------------
// One block (256 threads) per destination node. No global atomics.
#define CHUNK 64
template<int C, int F, int FPT, int ACT>
__global__ __launch_bounds__(256) void k_node_agg(
        const float* __restrict__ hpre,
        const float* __restrict__ bias,
        float* __restrict__ outp) {
    int node = blockIdx.x;
    int beg = g_rowstart[node], end = g_rowstart[node + 1];
    int deg = end - beg;
    int tid = threadIdx.x;

    __shared__ float s_adst[Hh];
    __shared__ float s_m[Hh], s_sum[Hh];
    __shared__ int   s_src[CHUNK];
    __shared__ float s_w[CHUNK][Hh];

    if (tid < Hh) {
        s_adst[tid] = g_adst[node * Hh + tid];
        s_m[tid] = -1e30f;
        s_sum[tid] = 0.f;
    }
    __syncthreads();

    int pairs = deg * Hh;
    // Phase A1: per-head max of leaky_relu(asrc[s]+adst[d])
    for (int i = tid; i < pairs; i += blockDim.x) {
        int e = i >> 3, h = i & 7;
        int s = g_csrc[beg + e];
        float a = g_asrc[s * Hh + h] + s_adst[h];
        a = (a > 0.f) ? a : 0.2f * a;
        atomicMaxFs(&s_m[h], a);
    }
    __syncthreads();
    // Phase A2: per-head sum of exp(alpha - m)
    for (int i = tid; i < pairs; i += blockDim.x) {
        int e = i >> 3, h = i & 7;
        int s = g_csrc[beg + e];
        float a = g_asrc[s * Hh + h] + s_adst[h];
        a = (a > 0.f) ? a : 0.2f * a;
        atomicAdd(&s_sum[h], expf(a - s_m[h]));
    }
    __syncthreads();
    if (tid < Hh) s_sum[tid] = 1.f / (s_sum[tid] + 1e-16f);
    __syncthreads();

    // Phase B: weighted aggregate, chunked over edges
    float acc[FPT];
    int   fidx[FPT];
    int   hidx[FPT];
    #pragma unroll
    for (int j = 0; j < FPT; j++) {
        acc[j] = 0.f;
        fidx[j] = tid + j * 256;
        hidx[j] = (fidx[j] < F) ? (fidx[j] / C) : 0;
    }

    for (int c0 = 0; c0 < deg; c0 += CHUNK) {
        int cn = min(CHUNK, deg - c0);
        for (int i = tid; i < cn * Hh; i += blockDim.x) {
            int e = i >> 3, h = i & 7;
            int s = g_csrc[beg + c0 + e];
            if (h == 0) s_src[e] = s;
            float a = g_asrc[s * Hh + h] + s_adst[h];
            a = (a > 0.f) ? a : 0.2f * a;
            s_w[e][h] = expf(a - s_m[h]) * s_sum[h];
        }
        __syncthreads();
        for (int e = 0; e < cn; e++) {
            const float* hp = hpre + (long)s_src[e] * F;
            #pragma unroll
            for (int j = 0; j < FPT; j++) {
                if (fidx[j] < F)
                    acc[j] += s_w[e][hidx[j]] * hp[fidx[j]];
            }
        }
        __syncthreads();
    }

    #pragma unroll
    for (int j = 0; j < FPT; j++) {
        if (fidx[j] < F) {
            float v = acc[j] + bias[fidx[j]];
            if (ACT) v = (v > 0.f) ? v : expm1f(v);   // ELU alpha=1
            outp[(long)node * F + fidx[j]] = v;
        }
    }
}

static inline int cdiv(long a, int b) { return (int)((a + b - 1) / b); }

extern "C" void kernel_launch(void* const* d_in, const int* in_sizes, int n_in,
                              void* d_out, int out_size) {
    const float* x    = (const float*)d_in[0];
    const void*  ei   = d_in[1];
    const float* W1   = (const float*)d_in[2];
    const float* a1s  = (const float*)d_in[3];
    const float* a1d  = (const float*)d_in[4];
    const float* b1   = (const float*)d_in[5];
    const float* W2   = (const float*)d_in[6];
    const float* a2s  = (const float*)d_in[7];
    const float* a2d  = (const float*)d_in[8];
    const float* b2   = (const float*)d_in[9];
    const float* Wlin = (const float*)d_in[10];
    const float* blin = (const float*)d_in[11];

    int E = in_sizes[1] / 2;
    int tot = E + Nn;
    float* out  = (float*)d_out;              // [N, NCLS]
    float* hout = out + (long)Nn * NCLSv;     // [N, F2]

    float *p_h1pre, *p_acc1, *p_h2pre;
    int *p_cnt;
    cudaGetSymbolAddress((void**)&p_h1pre, g_h1pre);
    cudaGetSymbolAddress((void**)&p_acc1,  g_acc1);
    cudaGetSymbolAddress((void**)&p_h2pre, g_h2pre);
    cudaGetSymbolAddress((void**)&p_cnt,   g_cnt);

    // ---- graph prep (CSR by destination; shared by both layers) ----
    k_detect_idx<<<1, 32>>>(ei);
    cudaMemsetAsync(p_cnt, 0, Nn * sizeof(int));
    k_prep<<<cdiv(tot, 256), 256>>>(ei, E);
    k_scan<<<1, 1024>>>();
    k_scatter<<<cdiv(tot, 256), 256>>>(tot);

    // ---- layer 1 ----
    k_sgemm<<<dim3(cdiv(F1v, BN), cdiv(Nn, BM)), 256>>>(x, W1, p_h1pre, Nn, FIN, F1v, nullptr);
    k_attn_coef<<<cdiv(Nn*Hh, 256), 256>>>(p_h1pre, a1s, a1d, C1v, F1v);
    k_node_agg<C1v, F1v, 1, 1><<<Nn, 256>>>(p_h1pre, b1, p_acc1);

    // ---- layer 2 ----
    k_sgemm<<<dim3(cdiv(F2v, BN), cdiv(Nn, BM)), 256>>>(p_acc1, W2, p_h2pre, Nn, F1v, F2v, nullptr);
    k_attn_coef<<<cdiv(Nn*Hh, 256), 256>>>(p_h2pre, a2s, a2d, CHv, F2v);
    k_node_agg<CHv, F2v, 2, 0><<<Nn, 256>>>(p_h2pre, b2, hout);

    // ---- classifier head ----
    k_sgemm<<<dim3(cdiv(NCLSv, BN), cdiv(Nn, BM)), 256>>>(hout, Wlin, out, Nn, F2v, NCLSv, blin);
}